// round 2
// baseline (speedup 1.0000x reference)
#include <cuda_runtime.h>
#include <cstdint>

#define T_LEN   4096
#define BATCH   512
#define CCH     16          // time steps per thread
#define NTHR    256
#define HALO    64
#define PITCH   34          // words per 16-step chunk (16*2 data + 2 pad) -> kills bank conflicts
#define SWORDS  (NTHR * PITCH)   // 8704 words per array
#define DT      0.005f

// Grid-wide reduction scratch (reset by the last block each launch -> graph-replay safe)
__device__ double       g_sum = 0.0;
__device__ unsigned int g_cnt = 0u;

__device__ __forceinline__ int pidx(int t) {
    // padded word index of timestep t (float2 slot, 8B-aligned since PITCH is even)
    return ((t >> 4) * PITCH) + ((t & 15) << 1);
}

extern "C" __global__ void __launch_bounds__(NTHR, 2)
kf_loss_kernel(const float* __restrict__ pred_vel,
               const float* __restrict__ targ_vel,
               const float* __restrict__ q_vel_p,
               const float* __restrict__ r_vel_p,
               float* __restrict__ out)
{
    extern __shared__ float smem[];
    float* sz = smem;               // staged pred_vel (padded)
    float* sw = smem + SWORDS;      // staged targ_vel (padded)
    float* sk = smem + 2 * SWORDS;  // (K1, K0) per t   (padded)

    __shared__ int    s_nstop;
    __shared__ float2 s_steady;
    __shared__ float  s_wsum[NTHR / 32];

    const int tid = threadIdx.x;
    const int bid = blockIdx.x;
    const int wid = tid >> 5;

    if (wid == 0) {
        // ---- gain (Riccati) recursion: serial, contracts with factor ~0.73 ----
        if (tid == 0) {
            const float qv = q_vel_p[0];
            const float r  = r_vel_p[0];
            float c = 1.0f, b = 0.0f;       // P0 = I per axis
            float pK1 = -1.0f, pK0 = -1.0f;
            int t = 0;
            for (; t < T_LEN; ++t) {
                float bp  = fmaf(DT, c, b);     // b' = b + dt*c
                float cp  = c + qv;             // c' = c + q_vel
                float S   = cp + r;
                float inv = __fdividef(1.0f, S);
                float K1  = cp * inv;
                float K0  = bp * inv;
                float rs  = r * inv;
                b = bp * rs;
                c = cp * rs;
                *(float2*)(sk + pidx(t)) = make_float2(K1, K0);
                bool conv = (fabsf(K1 - pK1) < 1e-6f) && (fabsf(K0 - pK0) < 1e-8f);
                pK1 = K1; pK0 = K0;
                if (conv) { ++t; break; }
            }
            s_nstop  = t;
            s_steady = make_float2(pK1, pK0);
        }
    } else {
        // ---- warps 1..7 stage this batch's data, coalesced float4 -> padded smem ----
        const int lid = tid - 32;               // 0..223
        const float4* gz = (const float4*)(pred_vel + (size_t)bid * T_LEN * 2);
        const float4* gw = (const float4*)(targ_vel + (size_t)bid * T_LEN * 2);
        for (int idx = lid; idx < T_LEN / 2; idx += (NTHR - 32)) {
            float4 vz = gz[idx];
            float4 vw = gw[idx];
            int t0 = idx * 2;
            int a0 = pidx(t0), a1 = pidx(t0 + 1);
            *(float2*)(sz + a0) = make_float2(vz.x, vz.y);
            *(float2*)(sz + a1) = make_float2(vz.z, vz.w);
            *(float2*)(sw + a0) = make_float2(vw.x, vw.y);
            *(float2*)(sw + a1) = make_float2(vw.z, vw.w);
        }
    }
    __syncthreads();

    // ---- fill converged (steady-state) tail of the gain table in parallel ----
    {
        const int    n0 = s_nstop;
        const float2 st = s_steady;
        for (int t = n0 + tid; t < T_LEN; t += NTHR)
            *(float2*)(sk + pidx(t)) = st;
    }
    __syncthreads();

    // ---- per-thread chunk: halo warm-up, then CCH loss terms ----
    const int i0     = tid * CCH;
    const int jstart = max(0, i0 - HALO);
    float vx = 0.0f, vy = 0.0f;

#pragma unroll 4
    for (int t = jstart; t < i0; ++t) {
        float2 z = *(const float2*)(sz + pidx(t));
        float2 k = *(const float2*)(sk + pidx(t));
        vx = fmaf(k.x, z.x - vx, vx);
        vy = fmaf(k.x, z.y - vy, vy);
    }

    const int iend = min(i0 + CCH, T_LEN - 1);
    float acc = 0.0f;
#pragma unroll 4
    for (int i = i0; i < iend; ++i) {
        float2 zi = *(const float2*)(sz + pidx(i));
        float2 ki = *(const float2*)(sk + pidx(i));
        vx = fmaf(ki.x, zi.x - vx, vx);              // v_i
        vy = fmaf(ki.x, zi.y - vy, vy);
        float2 zn = *(const float2*)(sz + pidx(i + 1));
        float2 kn = *(const float2*)(sk + pidx(i + 1));
        float2 wn = *(const float2*)(sw + pidx(i + 1));
        // pw - gw = dt*(v_i - w_{i+1}) + K0_{i+1}*(z_{i+1} - v_i)
        float ex = fmaf(DT, vx - wn.x, kn.y * (zn.x - vx));
        float ey = fmaf(DT, vy - wn.y, kn.y * (zn.y - vy));
        acc = fmaf(ex, ex, acc);
        acc = fmaf(ey, ey, acc);
    }

    // ---- block reduction ----
#pragma unroll
    for (int o = 16; o > 0; o >>= 1)
        acc += __shfl_xor_sync(0xFFFFFFFFu, acc, o);
    if ((tid & 31) == 0) s_wsum[wid] = acc;
    __syncthreads();

    if (tid == 0) {
        float bs = 0.0f;
#pragma unroll
        for (int i = 0; i < NTHR / 32; ++i) bs += s_wsum[i];

        atomicAdd(&g_sum, (double)bs);
        __threadfence();
        unsigned c = atomicAdd(&g_cnt, 1u);
        if (c == gridDim.x - 1) {
            double s = atomicAdd(&g_sum, 0.0);   // coherent read (includes own add)
            const double cnt = (double)BATCH * (double)(T_LEN - 1) * 2.0;
            out[0] = (float)(s / cnt);
            // reset scratch for the next graph replay
            g_sum = 0.0;
            g_cnt = 0u;
        }
    }
}

extern "C" void kernel_launch(void* const* d_in, const int* in_sizes, int n_in,
                              void* d_out, int out_size)
{
    const float* pred_vel = (const float*)d_in[0];   // (B, T, 2)
    const float* targ_vel = (const float*)d_in[1];   // (B, T, 2)
    // d_in[2] = q_pos (unused: position variance never feeds the gain)
    const float* q_vel    = (const float*)d_in[3];
    const float* r_vel    = (const float*)d_in[4];
    // d_in[5] = p0 (cancels in the windowed difference)
    float* out = (float*)d_out;

    const int smem_bytes = 3 * SWORDS * (int)sizeof(float);   // ~102 KB
    cudaFuncSetAttribute(kf_loss_kernel,
                         cudaFuncAttributeMaxDynamicSharedMemorySize, smem_bytes);

    kf_loss_kernel<<<BATCH, NTHR, smem_bytes>>>(pred_vel, targ_vel, q_vel, r_vel, out);
}

// round 3
// speedup vs baseline: 1.0118x; 1.0118x over previous
#include <cuda_runtime.h>
#include <cstdint>

#define T_LEN   4096
#define BATCH   512
#define CCH     16           // time steps per thread
#define NTHR    256
#define HALO    32           // 0.735^32 ~ 4e-5 contraction -> far under tolerance
#define PITCH   34           // words per 16-step chunk (32 data + 2 pad) -> conflict-free LDS
#define SWORDS  (NTHR * PITCH)   // 8704 words = 34.8 KB per array
#define TBL     128
#define DT      0.005f

// Grid-wide reduction scratch (reset by the last block each launch -> graph-replay safe)
__device__ double       g_sum = 0.0;
__device__ unsigned int g_cnt = 0u;

__device__ __forceinline__ int pidx(int t) {
    // padded word index of timestep t (float2 slot). Lane stride across chunks
    // = 34 words -> bank stride 2 -> conflict-free for 8B accesses.
    return ((t >> 4) * PITCH) + ((t & 15) << 1);
}

extern "C" __global__ void __launch_bounds__(NTHR, 3)
kf_loss_kernel(const float* __restrict__ pred_vel,
               const float* __restrict__ targ_vel,
               const float* __restrict__ q_vel_p,
               const float* __restrict__ r_vel_p,
               float* __restrict__ out)
{
    extern __shared__ float smem[];
    float* sz = smem;               // staged pred_vel (padded)
    float* sw = smem + SWORDS;      // staged targ_vel (padded)

    __shared__ float2 s_gtbl[TBL];          // (K1_t, K0_t) for t < 128; t>=128 == s_gtbl[127]
    __shared__ float  s_wsum[NTHR / 32];

    const int tid = threadIdx.x;
    const int bid = blockIdx.x;
    const int wid = tid >> 5;

    if (tid == 0) {
        // ---- Riccati gain recursion: contracts (factor ~0.735); fp32-converged << 128 ----
        const float qv = q_vel_p[0];
        const float r  = r_vel_p[0];
        float c = 1.0f, b = 0.0f;           // P0 = I per axis
#pragma unroll 4
        for (int t = 0; t < TBL; ++t) {
            float bp  = fmaf(DT, c, b);
            float cp  = c + qv;
            float inv = __fdividef(1.0f, cp + r);
            float rs  = r * inv;
            s_gtbl[t] = make_float2(cp * inv, bp * inv);
            b = bp * rs;
            c = cp * rs;
        }
    } else if (wid > 0) {
        // ---- warps 1..7 stage both arrays, coalesced float4 -> padded smem ----
        const int lid = tid - 32;           // 0..223
        const float4* gz = (const float4*)(pred_vel + (size_t)bid * T_LEN * 2);
        const float4* gw = (const float4*)(targ_vel + (size_t)bid * T_LEN * 2);
        for (int idx = lid; idx < T_LEN / 2; idx += (NTHR - 32)) {
            float4 vz = gz[idx];
            float4 vw = gw[idx];
            int t0 = idx * 2;
            int a0 = pidx(t0), a1 = pidx(t0 + 1);
            *(float2*)(sz + a0) = make_float2(vz.x, vz.y);
            *(float2*)(sz + a1) = make_float2(vz.z, vz.w);
            *(float2*)(sw + a0) = make_float2(vw.x, vw.y);
            *(float2*)(sw + a1) = make_float2(vw.z, vw.w);
        }
    }
    __syncthreads();

    const int i0     = tid * CCH;
    const int jstart = max(0, i0 - HALO);
    const int iend   = min(i0 + CCH, T_LEN - 1);

    float vx = 0.0f, vy = 0.0f;
    float acc = 0.0f;

    if (wid > 0) {
        // ================= steady-gain path (all t >= 128 here) =================
        const float2 ss  = s_gtbl[TBL - 1];
        const float K1   = ss.x;
        const float K0   = ss.y;
        const float dss  = 1.0f - K1;       // v <- dss*v + K1*z
        const float Ass  = DT - K0;         // ex = Ass*v - DT*w + K0*z_next

        // halo warm-up
#pragma unroll 8
        for (int t = jstart; t < i0; ++t) {
            float2 z = *(const float2*)(sz + pidx(t));
            vx = fmaf(dss, vx, K1 * z.x);
            vy = fmaf(dss, vy, K1 * z.y);
        }

        float2 zc = *(const float2*)(sz + pidx(i0));
#pragma unroll
        for (int i = i0; i < i0 + CCH; ++i) {
            if (i >= iend) break;
            vx = fmaf(dss, vx, K1 * zc.x);          // v_i
            vy = fmaf(dss, vy, K1 * zc.y);
            float2 zn = *(const float2*)(sz + pidx(i + 1));
            float2 wn = *(const float2*)(sw + pidx(i + 1));
            float ex = fmaf(Ass, vx, fmaf(-DT, wn.x, K0 * zn.x));
            float ey = fmaf(Ass, vy, fmaf(-DT, wn.y, K0 * zn.y));
            acc = fmaf(ex, ex, acc);
            acc = fmaf(ey, ey, acc);
            zc = zn;
        }
    } else {
        // ================= table path (warp 0: early, non-converged gains) =================
#pragma unroll 4
        for (int t = jstart; t < i0; ++t) {
            float2 z = *(const float2*)(sz + pidx(t));
            float K1 = s_gtbl[min(t, TBL - 1)].x;
            vx = fmaf(K1, z.x - vx, vx);
            vy = fmaf(K1, z.y - vy, vy);
        }

        float2 zc = *(const float2*)(sz + pidx(i0));
#pragma unroll 4
        for (int i = i0; i < iend; ++i) {
            float K1 = s_gtbl[min(i, TBL - 1)].x;
            vx = fmaf(K1, zc.x - vx, vx);           // v_i
            vy = fmaf(K1, zc.y - vy, vy);
            float K0n = s_gtbl[min(i + 1, TBL - 1)].y;
            float An  = DT - K0n;
            float2 zn = *(const float2*)(sz + pidx(i + 1));
            float2 wn = *(const float2*)(sw + pidx(i + 1));
            float ex = fmaf(An, vx, fmaf(-DT, wn.x, K0n * zn.x));
            float ey = fmaf(An, vy, fmaf(-DT, wn.y, K0n * zn.y));
            acc = fmaf(ex, ex, acc);
            acc = fmaf(ey, ey, acc);
            zc = zn;
        }
    }

    // ---- block reduction ----
#pragma unroll
    for (int o = 16; o > 0; o >>= 1)
        acc += __shfl_xor_sync(0xFFFFFFFFu, acc, o);
    if ((tid & 31) == 0) s_wsum[wid] = acc;
    __syncthreads();

    if (tid == 0) {
        float bs = 0.0f;
#pragma unroll
        for (int i = 0; i < NTHR / 32; ++i) bs += s_wsum[i];

        atomicAdd(&g_sum, (double)bs);
        __threadfence();
        unsigned c = atomicAdd(&g_cnt, 1u);
        if (c == gridDim.x - 1) {
            double s = atomicAdd(&g_sum, 0.0);   // coherent read (includes own add)
            const double cnt = (double)BATCH * (double)(T_LEN - 1) * 2.0;
            out[0] = (float)(s / cnt);
            // reset scratch for the next graph replay
            g_sum = 0.0;
            g_cnt = 0u;
        }
    }
}

extern "C" void kernel_launch(void* const* d_in, const int* in_sizes, int n_in,
                              void* d_out, int out_size)
{
    const float* pred_vel = (const float*)d_in[0];   // (B, T, 2)
    const float* targ_vel = (const float*)d_in[1];   // (B, T, 2)
    // d_in[2] = q_pos (never feeds the gain recursion)
    const float* q_vel    = (const float*)d_in[3];
    const float* r_vel    = (const float*)d_in[4];
    // d_in[5] = p0 (cancels in the windowed position difference)
    float* out = (float*)d_out;

    const int smem_bytes = 2 * SWORDS * (int)sizeof(float);   // ~69.6 KB -> 3 CTAs/SM
    cudaFuncSetAttribute(kf_loss_kernel,
                         cudaFuncAttributeMaxDynamicSharedMemorySize, smem_bytes);

    kf_loss_kernel<<<BATCH, NTHR, smem_bytes>>>(pred_vel, targ_vel, q_vel, r_vel, out);
}

// round 4
// speedup vs baseline: 1.2691x; 1.2542x over previous
#include <cuda_runtime.h>
#include <cstdint>

#define T_LEN   4096
#define BATCH   512
#define NTHR    512
#define WPB     (NTHR / 32)     // 16 warps per block
#define CHUNKS  8
#define CSZ     (T_LEN / CHUNKS)   // 512 timesteps per warp
#define TBL     128             // table region (gains converged well before this)
#define DT      0.005f
#define RS      64.0f           // rescale for linearized Riccati (keeps fp32 in range)

// Grid-wide reduction scratch (reset by last block each launch -> graph-replay safe)
__device__ double       g_sum = 0.0;
__device__ unsigned int g_cnt = 0u;

__device__ __forceinline__ float shup(float v, int o) {
    return __shfl_up_sync(0xffffffffu, v, o);
}

// one Kogge-Stone step with constant coefficient
#define SCAN_STEP(sxv, syv, coef, o)                          \
    {   float _a = shup(sxv, o), _b = shup(syv, o);           \
        if (lane >= o) {                                      \
            sxv = fmaf(coef, _a, sxv);                        \
            syv = fmaf(coef, _b, syv);                        \
        }                                                     \
    }

extern "C" __global__ void __launch_bounds__(NTHR, 2)
kf_loss_kernel(const float* __restrict__ pred_vel,
               const float* __restrict__ targ_vel,
               const float* __restrict__ q_vel_p,
               const float* __restrict__ r_vel_p,
               float* __restrict__ out)
{
    __shared__ float  sxa[TBL + 2], sya[TBL + 2], sua[TBL + 2];
    __shared__ float2 gt[TBL + 1];          // (K1_t, K0_t), t in [0, 128]
    __shared__ float  swsum[WPB];

    const int tid  = threadIdx.x;
    const int lane = tid & 31;
    const int wid  = tid >> 5;

    const float qv = q_vel_p[0];
    const float r  = r_vel_p[0];

    // ---- linearized Riccati: divisions off the serial chain ----
    // x_{t+1}=RS(r x + qv r y); y_{t+1}=RS(x+(qv+r)y); u_{t+1}=RS r(u + dt x)
    // K1_t = RS(x_t+qv y_t)/y_{t+1},  K0_t = RS(u_t+dt x_t)/y_{t+1}
    if (tid == 0) {
        float x = 1.0f, y = 1.0f, u = 0.0f;
        sxa[0] = x; sya[0] = y; sua[0] = u;
        const float c_xy = RS * r, c_xq = RS * qv * r;
        const float c_yy = RS * (qv + r), c_u = RS * r;
        for (int t = 1; t <= TBL + 1; ++t) {
            float xn = fmaf(c_xq, y, c_xy * x);
            float yn = fmaf(c_yy, y, RS * x);
            float un = c_u * fmaf(DT, x, u);
            x = xn; y = yn; u = un;
            sxa[t] = x; sya[t] = y; sua[t] = u;
        }
    }
    __syncthreads();
    if (tid <= TBL) {
        float xt = sxa[tid], yt = sya[tid], ut = sua[tid];
        float inv = RS / sya[tid + 1];
        gt[tid] = make_float2(fmaf(qv, yt, xt) * inv, fmaf(DT, xt, ut) * inv);
    }
    __syncthreads();

    // ---- per-warp chunk assignment ----
    const int wg    = blockIdx.x * WPB + wid;      // 0..4095
    const int row   = wg >> 3;
    const int chunk = wg & 7;
    const int c0    = chunk * CSZ;
    const int emax  = min(c0 + CSZ, T_LEN - 1);

    const float2* __restrict__ zr = (const float2*)pred_vel + (size_t)row * T_LEN;
    const float2* __restrict__ wr = (const float2*)targ_vel + (size_t)row * T_LEN;

    // steady-state constants
    const float2 gss = gt[TBL];
    const float  K1  = gss.x, K0 = gss.y;
    const float  dss = 1.0f - K1;              // v <- dss*v + K1*z
    const float  Ass = DT - K0;                // e = Ass*v - DT*w1 + K0*z1
    const float  d1 = dss, d2 = d1 * d1, d4 = d2 * d2, d8 = d4 * d4, d16 = d8 * d8;
    float dl = dss;                            // dss^(lane+1) for carry injection
    if (lane & 1)  dl *= d1;
    if (lane & 2)  dl *= d2;
    if (lane & 4)  dl *= d4;
    if (lane & 8)  dl *= d8;
    if (lane & 16) dl *= d16;

    float cx = 0.0f, cy = 0.0f;                // carry = v_{base-1}
    float acc = 0.0f;

    if (chunk == 0) {
        // ---- general (table-gain) region: t in [0, 128), variable-coefficient scan ----
        #pragma unroll 1
        for (int it = 0; it < TBL / 32; ++it) {
            int t = (it << 5) + lane;
            float2 z = zr[t];
            float2 g = gt[t];
            float  p  = 1.0f - g.x;
            float  sx = g.x * z.x, sy = g.x * z.y;
            #pragma unroll
            for (int o = 1; o < 32; o <<= 1) {
                float ax = shup(sx, o), ay = shup(sy, o), ap = shup(p, o);
                if (lane >= o) {
                    sx = fmaf(p, ax, sx);
                    sy = fmaf(p, ay, sy);
                    p *= ap;
                }
            }
            float vx = fmaf(p, cx, sx);
            float vy = fmaf(p, cy, sy);
            cx = __shfl_sync(0xffffffffu, vx, 31);
            cy = __shfl_sync(0xffffffffu, vy, 31);

            float2 g1 = gt[t + 1];
            float  an = DT - g1.y;
            float2 z1 = zr[t + 1];
            float2 w1 = wr[t + 1];
            float ex = fmaf(an, vx, fmaf(-DT, w1.x, g1.y * z1.x));
            float ey = fmaf(an, vy, fmaf(-DT, w1.y, g1.y * z1.y));
            acc = fmaf(ex, ex, acc);
            acc = fmaf(ey, ey, acc);
        }
    } else {
        // ---- halo: one steady scan iteration, carry only (error ~dss^32 ~ 5e-5) ----
        int t = c0 - 32 + lane;
        float2 z = zr[t];
        float sx = K1 * z.x, sy = K1 * z.y;
        SCAN_STEP(sx, sy, d1, 1)
        SCAN_STEP(sx, sy, d2, 2)
        SCAN_STEP(sx, sy, d4, 4)
        SCAN_STEP(sx, sy, d8, 8)
        SCAN_STEP(sx, sy, d16, 16)
        cx = __shfl_sync(0xffffffffu, sx, 31);
        cy = __shfl_sync(0xffffffffu, sy, 31);
    }

    // ---- steady-gain mainloop ----
    const int base0 = (chunk == 0) ? TBL : c0;
    #pragma unroll 4
    for (int base = base0; base < c0 + CSZ; base += 32) {
        int t = base + lane;
        float2 z = zr[t];
        float sx = K1 * z.x, sy = K1 * z.y;
        SCAN_STEP(sx, sy, d1, 1)
        SCAN_STEP(sx, sy, d2, 2)
        SCAN_STEP(sx, sy, d4, 4)
        SCAN_STEP(sx, sy, d8, 8)
        SCAN_STEP(sx, sy, d16, 16)
        float vx = fmaf(dl, cx, sx);
        float vy = fmaf(dl, cy, sy);
        cx = __shfl_sync(0xffffffffu, vx, 31);
        cy = __shfl_sync(0xffffffffu, vy, 31);

        int t1 = min(t + 1, T_LEN - 1);
        float2 z1 = zr[t1];
        float2 w1 = wr[t1];
        float ex = fmaf(Ass, vx, fmaf(-DT, w1.x, K0 * z1.x));
        float ey = fmaf(Ass, vy, fmaf(-DT, w1.y, K0 * z1.y));
        if (t < emax) {
            acc = fmaf(ex, ex, acc);
            acc = fmaf(ey, ey, acc);
        }
    }

    // ---- reduction ----
    #pragma unroll
    for (int o = 16; o > 0; o >>= 1)
        acc += __shfl_xor_sync(0xffffffffu, acc, o);
    if (lane == 0) swsum[wid] = acc;
    __syncthreads();

    if (tid == 0) {
        float bs = 0.0f;
        #pragma unroll
        for (int i = 0; i < WPB; ++i) bs += swsum[i];

        atomicAdd(&g_sum, (double)bs);
        __threadfence();
        unsigned c = atomicAdd(&g_cnt, 1u);
        if (c == gridDim.x - 1) {
            double s = atomicAdd(&g_sum, 0.0);    // coherent read (includes own add)
            const double cnt = (double)BATCH * (double)(T_LEN - 1) * 2.0;
            out[0] = (float)(s / cnt);
            g_sum = 0.0;                          // reset for next graph replay
            g_cnt = 0u;
        }
    }
}

extern "C" void kernel_launch(void* const* d_in, const int* in_sizes, int n_in,
                              void* d_out, int out_size)
{
    const float* pred_vel = (const float*)d_in[0];   // (B, T, 2)
    const float* targ_vel = (const float*)d_in[1];   // (B, T, 2)
    // d_in[2] = q_pos (never feeds the gain recursion)
    const float* q_vel    = (const float*)d_in[3];
    const float* r_vel    = (const float*)d_in[4];
    // d_in[5] = p0 (cancels in the windowed position difference)
    float* out = (float*)d_out;

    const int nblocks = (BATCH * CHUNKS) / WPB;      // 256 blocks, one wave
    kf_loss_kernel<<<nblocks, NTHR>>>(pred_vel, targ_vel, q_vel, r_vel, out);
}